// round 5
// baseline (speedup 1.0000x reference)
#include <cuda_runtime.h>
#include <cuda_bf16.h>
#include <cstdint>

#define N_EDGES 800000
#define N_NODES 50000
#define MID 3
#define NVEC 32

// Per-node accumulators: [N_NODES, MID, NVEC] floats, viewed as float4.
// 50000 * 96 floats = 4.8M floats = 1.2M float4 each (18.3 MB each; both fit in L2).
__device__ float4 g_xn1[N_NODES * MID * NVEC / 4];
__device__ float4 g_xn2[N_NODES * MID * NVEC / 4];

__device__ __forceinline__ void red_add_v4(float4* addr, float4 v) {
    asm volatile("red.global.add.v4.f32 [%0], {%1, %2, %3, %4};"
                 :: "l"(addr), "f"(v.x), "f"(v.y), "f"(v.z), "f"(v.w)
                 : "memory");
}

// ---------------------------------------------------------------------------
// Kernel 1: zero the accumulators (graph-capturable; no memset API needed)
// ---------------------------------------------------------------------------
__global__ void zero_accum_kernel() {
    int i = blockIdx.x * blockDim.x + threadIdx.x;
    const float4 z = make_float4(0.f, 0.f, 0.f, 0.f);
    if (i < N_NODES * MID * NVEC / 4) {
        g_xn1[i] = z;
        g_xn2[i] = z;
    }
}

// ---------------------------------------------------------------------------
// Kernel 2: edge scatter.  8 threads per edge; each thread owns 4 of the 32
// vector lanes (float4).  W read once per edge, reused across MID=3.
// wxe = W * xe scattered with red.v4 into xn1[dst] and xn2[src].
// ---------------------------------------------------------------------------
__global__ void edge_scatter_kernel(const float4* __restrict__ xe4,   // [E*3*8]
                                    const float4* __restrict__ W4,    // [E*8]
                                    const int*    __restrict__ src,
                                    const int*    __restrict__ dst) {
    int gid = blockIdx.x * blockDim.x + threadIdx.x;
    int e   = gid >> 3;
    int sub = gid & 7;
    if (e >= N_EDGES) return;

    float4 w = __ldg(&W4[e * 8 + sub]);
    int d = __ldg(&dst[e]);
    int s = __ldg(&src[e]);

    float4* p1 = &g_xn1[d * (MID * 8) + sub];
    float4* p2 = &g_xn2[s * (MID * 8) + sub];

#pragma unroll
    for (int m = 0; m < MID; m++) {
        float4 x = __ldg(&xe4[(e * MID + m) * 8 + sub]);
        float4 v;
        v.x = w.x * x.x;
        v.y = w.y * x.y;
        v.z = w.z * x.z;
        v.w = w.w * x.w;
        red_add_v4(p1 + m * 8, v);
        red_add_v4(p2 + m * 8, v);
    }
}

// ---------------------------------------------------------------------------
// Kernel 3: per-node epilogue.
//   out = xn1 @ Ma + xn2 @ Mb, Ma = 0.5*(M1+M2), Mb = 0.5*(M2-M1)
// One warp per node.  Lane v holds xn rows; results built by shuffle
// broadcast against Ma/Mb staged in shared memory.
// ---------------------------------------------------------------------------
__global__ void node_mix_kernel(const float* __restrict__ M1,
                                const float* __restrict__ M2,
                                float* __restrict__ out) {
    __shared__ float sMa[NVEC * NVEC];
    __shared__ float sMb[NVEC * NVEC];

    for (int i = threadIdx.x; i < NVEC * NVEC; i += blockDim.x) {
        float m1 = M1[i], m2 = M2[i];
        sMa[i] = 0.5f * (m1 + m2);
        sMb[i] = 0.5f * (m2 - m1);
    }
    __syncthreads();

    int gwarp = (blockIdx.x * blockDim.x + threadIdx.x) >> 5;
    int lane  = threadIdx.x & 31;
    if (gwarp >= N_NODES) return;

    const float* x1 = reinterpret_cast<const float*>(g_xn1) + gwarp * (MID * NVEC);
    const float* x2 = reinterpret_cast<const float*>(g_xn2) + gwarp * (MID * NVEC);

    float a1_0 = x1[lane],          a2_0 = x2[lane];
    float a1_1 = x1[NVEC + lane],   a2_1 = x2[NVEC + lane];
    float a1_2 = x1[2*NVEC + lane], a2_2 = x2[2*NVEC + lane];

    float o0 = 0.f, o1 = 0.f, o2 = 0.f;
#pragma unroll
    for (int v = 0; v < NVEC; v++) {
        float b1 = sMa[v * NVEC + lane];
        float b2 = sMb[v * NVEC + lane];
        o0 = fmaf(__shfl_sync(0xffffffffu, a1_0, v), b1,
             fmaf(__shfl_sync(0xffffffffu, a2_0, v), b2, o0));
        o1 = fmaf(__shfl_sync(0xffffffffu, a1_1, v), b1,
             fmaf(__shfl_sync(0xffffffffu, a2_1, v), b2, o1));
        o2 = fmaf(__shfl_sync(0xffffffffu, a1_2, v), b1,
             fmaf(__shfl_sync(0xffffffffu, a2_2, v), b2, o2));
    }

    float* o = out + gwarp * (MID * NVEC);
    o[lane]          = o0;
    o[NVEC + lane]   = o1;
    o[2*NVEC + lane] = o2;
}

// ---------------------------------------------------------------------------
// Launch.  Inputs (metadata order): xe, W, M1, M2, xe_src, xe_dst, n_nodes
// ---------------------------------------------------------------------------
extern "C" void kernel_launch(void* const* d_in, const int* in_sizes, int n_in,
                              void* d_out, int out_size) {
    const float4* xe4 = (const float4*)d_in[0];
    const float4* W4  = (const float4*)d_in[1];
    const float*  M1  = (const float*)d_in[2];
    const float*  M2  = (const float*)d_in[3];
    const int*    src = (const int*)d_in[4];
    const int*    dst = (const int*)d_in[5];
    float* out = (float*)d_out;

    // 1) zero accumulators
    {
        int n = N_NODES * MID * NVEC / 4;
        zero_accum_kernel<<<(n + 255) / 256, 256>>>();
    }
    // 2) edge scatter (8 threads per edge)
    {
        long long nthreads = (long long)N_EDGES * 8;
        int blocks = (int)((nthreads + 255) / 256);
        edge_scatter_kernel<<<blocks, 256>>>(xe4, W4, src, dst);
    }
    // 3) per-node mix (one warp per node)
    {
        long long nthreads = (long long)N_NODES * 32;
        int blocks = (int)((nthreads + 255) / 256);
        node_mix_kernel<<<blocks, 256>>>(M1, M2, out);
    }
}

// round 6
// speedup vs baseline: 1.0057x; 1.0057x over previous
#include <cuda_runtime.h>
#include <cuda_bf16.h>
#include <cstdint>

#define N_EDGES 800000
#define N_NODES 50000
#define MID 3
#define NVEC 32

// Per-node accumulators: [N_NODES, MID, NVEC] floats, viewed as float4.
// 50000 * 96 floats = 4.8M floats = 1.2M float4 each (18.3 MB each; both fit in L2).
__device__ float4 g_xn1[N_NODES * MID * NVEC / 4];
__device__ float4 g_xn2[N_NODES * MID * NVEC / 4];

__device__ __forceinline__ void red_add_v4(float4* addr, float4 v) {
    asm volatile("red.global.add.v4.f32 [%0], {%1, %2, %3, %4};"
                 :: "l"(addr), "f"(v.x), "f"(v.y), "f"(v.z), "f"(v.w)
                 : "memory");
}

// ---------------------------------------------------------------------------
// Kernel 1: zero the accumulators (graph-capturable; no memset API needed)
// ---------------------------------------------------------------------------
__global__ void zero_accum_kernel() {
    int i = blockIdx.x * blockDim.x + threadIdx.x;
    const float4 z = make_float4(0.f, 0.f, 0.f, 0.f);
    if (i < N_NODES * MID * NVEC / 4) {
        g_xn1[i] = z;
        g_xn2[i] = z;
    }
}

// ---------------------------------------------------------------------------
// Kernel 2: edge scatter.  8 threads per edge; each thread owns 4 of the 32
// vector lanes (float4).  W read once per edge, reused across MID=3.
// wxe = W * xe scattered with red.v4 into xn1[dst] and xn2[src].
// ---------------------------------------------------------------------------
__global__ void edge_scatter_kernel(const float4* __restrict__ xe4,   // [E*3*8]
                                    const float4* __restrict__ W4,    // [E*8]
                                    const int*    __restrict__ src,
                                    const int*    __restrict__ dst) {
    int gid = blockIdx.x * blockDim.x + threadIdx.x;
    int e   = gid >> 3;
    int sub = gid & 7;
    if (e >= N_EDGES) return;

    float4 w = __ldg(&W4[e * 8 + sub]);
    int d = __ldg(&dst[e]);
    int s = __ldg(&src[e]);

    float4* p1 = &g_xn1[d * (MID * 8) + sub];
    float4* p2 = &g_xn2[s * (MID * 8) + sub];

#pragma unroll
    for (int m = 0; m < MID; m++) {
        float4 x = __ldg(&xe4[(e * MID + m) * 8 + sub]);
        float4 v;
        v.x = w.x * x.x;
        v.y = w.y * x.y;
        v.z = w.z * x.z;
        v.w = w.w * x.w;
        red_add_v4(p1 + m * 8, v);
        red_add_v4(p2 + m * 8, v);
    }
}

// ---------------------------------------------------------------------------
// Kernel 3: per-node epilogue.
//   out = xn1 @ Ma + xn2 @ Mb, Ma = 0.5*(M1+M2), Mb = 0.5*(M2-M1)
// One warp per node.  Lane v holds xn rows; results built by shuffle
// broadcast against Ma/Mb staged in shared memory.
// ---------------------------------------------------------------------------
__global__ void node_mix_kernel(const float* __restrict__ M1,
                                const float* __restrict__ M2,
                                float* __restrict__ out) {
    __shared__ float sMa[NVEC * NVEC];
    __shared__ float sMb[NVEC * NVEC];

    for (int i = threadIdx.x; i < NVEC * NVEC; i += blockDim.x) {
        float m1 = M1[i], m2 = M2[i];
        sMa[i] = 0.5f * (m1 + m2);
        sMb[i] = 0.5f * (m2 - m1);
    }
    __syncthreads();

    int gwarp = (blockIdx.x * blockDim.x + threadIdx.x) >> 5;
    int lane  = threadIdx.x & 31;
    if (gwarp >= N_NODES) return;

    const float* x1 = reinterpret_cast<const float*>(g_xn1) + gwarp * (MID * NVEC);
    const float* x2 = reinterpret_cast<const float*>(g_xn2) + gwarp * (MID * NVEC);

    float a1_0 = x1[lane],          a2_0 = x2[lane];
    float a1_1 = x1[NVEC + lane],   a2_1 = x2[NVEC + lane];
    float a1_2 = x1[2*NVEC + lane], a2_2 = x2[2*NVEC + lane];

    float o0 = 0.f, o1 = 0.f, o2 = 0.f;
#pragma unroll
    for (int v = 0; v < NVEC; v++) {
        float b1 = sMa[v * NVEC + lane];
        float b2 = sMb[v * NVEC + lane];
        o0 = fmaf(__shfl_sync(0xffffffffu, a1_0, v), b1,
             fmaf(__shfl_sync(0xffffffffu, a2_0, v), b2, o0));
        o1 = fmaf(__shfl_sync(0xffffffffu, a1_1, v), b1,
             fmaf(__shfl_sync(0xffffffffu, a2_1, v), b2, o1));
        o2 = fmaf(__shfl_sync(0xffffffffu, a1_2, v), b1,
             fmaf(__shfl_sync(0xffffffffu, a2_2, v), b2, o2));
    }

    float* o = out + gwarp * (MID * NVEC);
    o[lane]          = o0;
    o[NVEC + lane]   = o1;
    o[2*NVEC + lane] = o2;
}

// ---------------------------------------------------------------------------
// Launch.  Inputs (metadata order): xe, W, M1, M2, xe_src, xe_dst, n_nodes
// ---------------------------------------------------------------------------
extern "C" void kernel_launch(void* const* d_in, const int* in_sizes, int n_in,
                              void* d_out, int out_size) {
    const float4* xe4 = (const float4*)d_in[0];
    const float4* W4  = (const float4*)d_in[1];
    const float*  M1  = (const float*)d_in[2];
    const float*  M2  = (const float*)d_in[3];
    const int*    src = (const int*)d_in[4];
    const int*    dst = (const int*)d_in[5];
    float* out = (float*)d_out;

    // 1) zero accumulators
    {
        int n = N_NODES * MID * NVEC / 4;
        zero_accum_kernel<<<(n + 255) / 256, 256>>>();
    }
    // 2) edge scatter (8 threads per edge)
    {
        long long nthreads = (long long)N_EDGES * 8;
        int blocks = (int)((nthreads + 255) / 256);
        edge_scatter_kernel<<<blocks, 256>>>(xe4, W4, src, dst);
    }
    // 3) per-node mix (one warp per node)
    {
        long long nthreads = (long long)N_NODES * 32;
        int blocks = (int)((nthreads + 255) / 256);
        node_mix_kernel<<<blocks, 256>>>(M1, M2, out);
    }
}

// round 7
// speedup vs baseline: 1.0092x; 1.0035x over previous
#include <cuda_runtime.h>
#include <cuda_bf16.h>
#include <cstdint>

#define N_EDGES 800000
#define N_NODES 50000
#define MID 3
#define NVEC 32

// Per-node accumulators: [N_NODES, MID, NVEC] floats, viewed as float4.
// 50000 * 96 floats = 4.8M floats = 1.2M float4 each (18.3 MB each; both fit in L2).
__device__ float4 g_xn1[N_NODES * MID * NVEC / 4];
__device__ float4 g_xn2[N_NODES * MID * NVEC / 4];

__device__ __forceinline__ void red_add_v4(float4* addr, float4 v) {
    asm volatile("red.global.add.v4.f32 [%0], {%1, %2, %3, %4};"
                 :: "l"(addr), "f"(v.x), "f"(v.y), "f"(v.z), "f"(v.w)
                 : "memory");
}

// ---------------------------------------------------------------------------
// Kernel 1: zero the accumulators (graph-capturable; no memset API needed)
// ---------------------------------------------------------------------------
__global__ void zero_accum_kernel() {
    int i = blockIdx.x * blockDim.x + threadIdx.x;
    const float4 z = make_float4(0.f, 0.f, 0.f, 0.f);
    if (i < N_NODES * MID * NVEC / 4) {
        g_xn1[i] = z;
        g_xn2[i] = z;
    }
}

// ---------------------------------------------------------------------------
// Kernel 2: edge scatter.  8 threads per edge; each thread owns 4 of the 32
// vector lanes (float4).  W read once per edge, reused across MID=3.
// wxe = W * xe scattered with red.v4 into xn1[dst] and xn2[src].
// ---------------------------------------------------------------------------
__global__ void edge_scatter_kernel(const float4* __restrict__ xe4,   // [E*3*8]
                                    const float4* __restrict__ W4,    // [E*8]
                                    const int*    __restrict__ src,
                                    const int*    __restrict__ dst) {
    int gid = blockIdx.x * blockDim.x + threadIdx.x;
    int e   = gid >> 3;
    int sub = gid & 7;
    if (e >= N_EDGES) return;

    float4 w = __ldg(&W4[e * 8 + sub]);
    int d = __ldg(&dst[e]);
    int s = __ldg(&src[e]);

    float4* p1 = &g_xn1[d * (MID * 8) + sub];
    float4* p2 = &g_xn2[s * (MID * 8) + sub];

#pragma unroll
    for (int m = 0; m < MID; m++) {
        float4 x = __ldg(&xe4[(e * MID + m) * 8 + sub]);
        float4 v;
        v.x = w.x * x.x;
        v.y = w.y * x.y;
        v.z = w.z * x.z;
        v.w = w.w * x.w;
        red_add_v4(p1 + m * 8, v);
        red_add_v4(p2 + m * 8, v);
    }
}

// ---------------------------------------------------------------------------
// Kernel 3: per-node epilogue.
//   out = xn1 @ Ma + xn2 @ Mb, Ma = 0.5*(M1+M2), Mb = 0.5*(M2-M1)
// One warp per node.  Lane v holds xn rows; results built by shuffle
// broadcast against Ma/Mb staged in shared memory.
// ---------------------------------------------------------------------------
__global__ void node_mix_kernel(const float* __restrict__ M1,
                                const float* __restrict__ M2,
                                float* __restrict__ out) {
    __shared__ float sMa[NVEC * NVEC];
    __shared__ float sMb[NVEC * NVEC];

    for (int i = threadIdx.x; i < NVEC * NVEC; i += blockDim.x) {
        float m1 = M1[i], m2 = M2[i];
        sMa[i] = 0.5f * (m1 + m2);
        sMb[i] = 0.5f * (m2 - m1);
    }
    __syncthreads();

    int gwarp = (blockIdx.x * blockDim.x + threadIdx.x) >> 5;
    int lane  = threadIdx.x & 31;
    if (gwarp >= N_NODES) return;

    const float* x1 = reinterpret_cast<const float*>(g_xn1) + gwarp * (MID * NVEC);
    const float* x2 = reinterpret_cast<const float*>(g_xn2) + gwarp * (MID * NVEC);

    float a1_0 = x1[lane],          a2_0 = x2[lane];
    float a1_1 = x1[NVEC + lane],   a2_1 = x2[NVEC + lane];
    float a1_2 = x1[2*NVEC + lane], a2_2 = x2[2*NVEC + lane];

    float o0 = 0.f, o1 = 0.f, o2 = 0.f;
#pragma unroll
    for (int v = 0; v < NVEC; v++) {
        float b1 = sMa[v * NVEC + lane];
        float b2 = sMb[v * NVEC + lane];
        o0 = fmaf(__shfl_sync(0xffffffffu, a1_0, v), b1,
             fmaf(__shfl_sync(0xffffffffu, a2_0, v), b2, o0));
        o1 = fmaf(__shfl_sync(0xffffffffu, a1_1, v), b1,
             fmaf(__shfl_sync(0xffffffffu, a2_1, v), b2, o1));
        o2 = fmaf(__shfl_sync(0xffffffffu, a1_2, v), b1,
             fmaf(__shfl_sync(0xffffffffu, a2_2, v), b2, o2));
    }

    float* o = out + gwarp * (MID * NVEC);
    o[lane]          = o0;
    o[NVEC + lane]   = o1;
    o[2*NVEC + lane] = o2;
}

// ---------------------------------------------------------------------------
// Launch.  Inputs (metadata order): xe, W, M1, M2, xe_src, xe_dst, n_nodes
// ---------------------------------------------------------------------------
extern "C" void kernel_launch(void* const* d_in, const int* in_sizes, int n_in,
                              void* d_out, int out_size) {
    const float4* xe4 = (const float4*)d_in[0];
    const float4* W4  = (const float4*)d_in[1];
    const float*  M1  = (const float*)d_in[2];
    const float*  M2  = (const float*)d_in[3];
    const int*    src = (const int*)d_in[4];
    const int*    dst = (const int*)d_in[5];
    float* out = (float*)d_out;

    // 1) zero accumulators
    {
        int n = N_NODES * MID * NVEC / 4;
        zero_accum_kernel<<<(n + 255) / 256, 256>>>();
    }
    // 2) edge scatter (8 threads per edge)
    {
        long long nthreads = (long long)N_EDGES * 8;
        int blocks = (int)((nthreads + 255) / 256);
        edge_scatter_kernel<<<blocks, 256>>>(xe4, W4, src, dst);
    }
    // 3) per-node mix (one warp per node)
    {
        long long nthreads = (long long)N_NODES * 32;
        int blocks = (int)((nthreads + 255) / 256);
        node_mix_kernel<<<blocks, 256>>>(M1, M2, out);
    }
}